// round 9
// baseline (speedup 1.0000x reference)
#include <cuda_runtime.h>
#include <cuda_fp16.h>
#include <cstdint>
#include <math.h>

// Problem dims (fixed): nx=ny=8192, d=1024, K=512, n_iters=50
#define NX 8192
#define D_DIM 1024
#define KANC 512
#define NITERS 50
#define COLCH 64          // y-blocks in the column pass (128 rows each)
#define EPS_INV 20.0f

// ---------------- scratch ----------------------------------------------------
__device__ __align__(16) __half g_K[(size_t)NX * NX];      // exp(cos/eps), 128 MB
__device__ __align__(16) float g_SimX[(size_t)NX * KANC];
__device__ __align__(16) float g_SimY[(size_t)NX * KANC];
__device__ __align__(16) float g_invX[NX];
__device__ __align__(16) float g_invY[NX];
__device__ __align__(16) float g_invAX[KANC];
__device__ __align__(16) float g_invAY[KANC];
__device__ __align__(16) float g_invSX[NX];
__device__ __align__(16) float g_invSY[NX];
__device__ __align__(16) float g_a[NX];
__device__ __align__(16) float g_b[NX];
__device__ __align__(16) float g_la[NX];
__device__ __align__(16) float g_lb[NX];
__device__ __align__(16) float g_part[(size_t)COLCH * NX];
__device__ int g_cnt[8];   // zero-init; self-resetting finisher counters

// ---------------- f32x2 helpers ----------------------------------------------
__device__ __forceinline__ unsigned long long pack2(float x, float y) {
    unsigned long long r;
    asm("mov.b64 %0, {%1, %2};" : "=l"(r) : "f"(x), "f"(y));
    return r;
}
__device__ __forceinline__ void unpack2(unsigned long long p, float& x, float& y) {
    asm("mov.b64 {%0, %1}, %2;" : "=f"(x), "=f"(y) : "l"(p));
}
__device__ __forceinline__ unsigned long long fma2(unsigned long long a,
                                                   unsigned long long b,
                                                   unsigned long long c) {
    unsigned long long d;
    asm("fma.rn.f32x2 %0, %1, %2, %3;" : "=l"(d) : "l"(a), "l"(b), "l"(c));
    return d;
}

// ---------------- row L2-norm ------------------------------------------------
__global__ void __launch_bounds__(256) rownorm_kernel(const float* __restrict__ A,
                                                      float* __restrict__ inv, int ncols) {
    int row = blockIdx.x;
    const float4* a4 = (const float4*)(A + (size_t)row * ncols);
    int n4 = ncols >> 2;
    float s = 0.f;
    for (int c = threadIdx.x; c < n4; c += 256) {
        float4 x = a4[c];
        s += x.x * x.x + x.y * x.y + x.z * x.z + x.w * x.w;
    }
#pragma unroll
    for (int o = 16; o; o >>= 1) s += __shfl_xor_sync(0xffffffffu, s, o);
    __shared__ float red[8];
    int lane = threadIdx.x & 31, wid = threadIdx.x >> 5;
    if (lane == 0) red[wid] = s;
    __syncthreads();
    if (threadIdx.x == 0) {
        float t = 0.f;
#pragma unroll
        for (int w = 0; w < 8; w++) t += red[w];
        inv[row] = 1.0f / fmaxf(sqrtf(t), 1e-8f);
    }
}

// ---------------- NT GEMM (f32x2, A-dup smem); fp32 out or exp->fp16 out -----
#define GBM 128
#define GBN 128
#define GBK 16
#define ASTR 260          // A-dup row stride (words): 16B-aligned rows (260%4==0)
#define BSTR 132          // Bs row stride (words): 16B-aligned rows

__global__ void __launch_bounds__(256) gemm_nt_kernel(const float* __restrict__ A,
                                                      const float* __restrict__ B,
                                                      float* __restrict__ C,
                                                      __half* __restrict__ Ch,
                                                      const float* __restrict__ sa,
                                                      const float* __restrict__ sb,
                                                      int M, int N, int K, float alpha,
                                                      int do_exp) {
    __shared__ float As[GBK][ASTR];   // duplicated: As[k][2r]=As[k][2r+1]=A[r][k]
    __shared__ float Bs[GBK][BSTR];
    int tid = threadIdx.x;
    int bm = blockIdx.y, bn = blockIdx.x;
    const float* Ab = A + (size_t)bm * GBM * K;
    const float* Bb = B + (size_t)bn * GBN * K;

    int tx = tid & 15;          // N dir (4+4 cols)
    int ty = tid >> 4;          // M dir (4+4 rows)
    int lr = tid >> 2;          // loader row
    int lc = (tid & 3) * 4;     // loader col (k)

    unsigned long long acc[8][4];   // [i-row][j-pair]
#pragma unroll
    for (int i = 0; i < 8; i++)
#pragma unroll
        for (int jp = 0; jp < 4; jp++) acc[i][jp] = 0ULL;

    for (int k0 = 0; k0 < K; k0 += GBK) {
#pragma unroll
        for (int sgm = 0; sgm < 2; sgm++) {
            int r = lr + 64 * sgm;
            float4 a4 = *(const float4*)(Ab + (size_t)r * K + k0 + lc);
            As[lc + 0][2 * r] = a4.x; As[lc + 0][2 * r + 1] = a4.x;
            As[lc + 1][2 * r] = a4.y; As[lc + 1][2 * r + 1] = a4.y;
            As[lc + 2][2 * r] = a4.z; As[lc + 2][2 * r + 1] = a4.z;
            As[lc + 3][2 * r] = a4.w; As[lc + 3][2 * r + 1] = a4.w;
            float4 b4 = *(const float4*)(Bb + (size_t)r * K + k0 + lc);
            Bs[lc + 0][r] = b4.x; Bs[lc + 1][r] = b4.y;
            Bs[lc + 2][r] = b4.z; Bs[lc + 3][r] = b4.w;
        }
        __syncthreads();
#pragma unroll
        for (int kk = 0; kk < GBK; kk++) {
            float4 ad0 = *(const float4*)&As[kk][ty * 8];          // (a0,a0,a1,a1)
            float4 ad1 = *(const float4*)&As[kk][ty * 8 + 4];      // (a2,a2,a3,a3)
            float4 ad2 = *(const float4*)&As[kk][ty * 8 + 128];    // rows +64
            float4 ad3 = *(const float4*)&As[kk][ty * 8 + 132];
            float4 b0 = *(const float4*)&Bs[kk][tx * 4];
            float4 b1 = *(const float4*)&Bs[kk][tx * 4 + 64];
            unsigned long long as2[8], bp[4];
            as2[0] = pack2(ad0.x, ad0.y); as2[1] = pack2(ad0.z, ad0.w);
            as2[2] = pack2(ad1.x, ad1.y); as2[3] = pack2(ad1.z, ad1.w);
            as2[4] = pack2(ad2.x, ad2.y); as2[5] = pack2(ad2.z, ad2.w);
            as2[6] = pack2(ad3.x, ad3.y); as2[7] = pack2(ad3.z, ad3.w);
            bp[0] = pack2(b0.x, b0.y); bp[1] = pack2(b0.z, b0.w);
            bp[2] = pack2(b1.x, b1.y); bp[3] = pack2(b1.z, b1.w);
#pragma unroll
            for (int i = 0; i < 8; i++)
#pragma unroll
                for (int jp = 0; jp < 4; jp++) acc[i][jp] = fma2(as2[i], bp[jp], acc[i][jp]);
        }
        __syncthreads();
    }

#pragma unroll
    for (int i = 0; i < 8; i++) {
        int row = bm * GBM + ty * 4 + ((i < 4) ? (i >> 1) * 2 + (i & 1) : 64 + (i - 4));
        // i in 0..3 -> rows ty*4 + 0..3 ; i in 4..7 -> rows ty*4 + 64 + 0..3
        row = bm * GBM + ty * 4 + ((i < 4) ? i : (60 + i));   // 60+i = 64 + (i-4)
        float si = sa[row] * alpha;
#pragma unroll
        for (int g = 0; g < 2; g++) {
            int col = bn * GBN + tx * 4 + (g << 6);
            float v0, v1, v2, v3;
            unpack2(acc[i][g * 2], v0, v1);
            unpack2(acc[i][g * 2 + 1], v2, v3);
            float4 o;
            o.x = v0 * si * sb[col + 0];
            o.y = v1 * si * sb[col + 1];
            o.z = v2 * si * sb[col + 2];
            o.w = v3 * si * sb[col + 3];
            if (do_exp) {
                __half2 h0 = __floats2half2_rn(__expf(o.x), __expf(o.y));
                __half2 h1 = __floats2half2_rn(__expf(o.z), __expf(o.w));
                uint2 pkv;
                pkv.x = *(unsigned int*)&h0;
                pkv.y = *(unsigned int*)&h1;
                *(uint2*)(Ch + (size_t)row * N + col) = pkv;
            } else {
                *(float4*)(C + (size_t)row * N + col) = o;
            }
        }
    }
}

// ---------------- row matvec: a_i = mu / sum_j K_ij b_j ----------------------
__global__ void __launch_bounds__(256) row_matvec_kernel(const __half* __restrict__ Km,
                                                         const float* __restrict__ b,
                                                         float* __restrict__ a, float mu) {
    int r0 = blockIdx.x * 4;
    const uint4* row0 = (const uint4*)(Km + (size_t)r0 * NX);
    const float4* b4 = (const float4*)b;
    float s0 = 0.f, s1 = 0.f, s2 = 0.f, s3 = 0.f;
#pragma unroll
    for (int it = 0; it < NX / 8 / 256; it++) {
        int c = it * 256 + threadIdx.x;
        float4 bb0 = b4[c * 2], bb1 = b4[c * 2 + 1];
        float bv[8] = {bb0.x, bb0.y, bb0.z, bb0.w, bb1.x, bb1.y, bb1.z, bb1.w};
#pragma unroll
        for (int r = 0; r < 4; r++) {
            uint4 x = row0[c + r * (NX / 8)];
            const __half2* hx = (const __half2*)&x;
            float accv = 0.f;
#pragma unroll
            for (int q = 0; q < 4; q++) {
                float2 f = __half22float2(hx[q]);
                accv += f.x * bv[q * 2] + f.y * bv[q * 2 + 1];
            }
            if (r == 0) s0 += accv;
            else if (r == 1) s1 += accv;
            else if (r == 2) s2 += accv;
            else s3 += accv;
        }
    }
#pragma unroll
    for (int o = 16; o; o >>= 1) {
        s0 += __shfl_xor_sync(0xffffffffu, s0, o);
        s1 += __shfl_xor_sync(0xffffffffu, s1, o);
        s2 += __shfl_xor_sync(0xffffffffu, s2, o);
        s3 += __shfl_xor_sync(0xffffffffu, s3, o);
    }
    __shared__ float red[8][4];
    int lane = threadIdx.x & 31, wid = threadIdx.x >> 5;
    if (lane == 0) { red[wid][0] = s0; red[wid][1] = s1; red[wid][2] = s2; red[wid][3] = s3; }
    __syncthreads();
    if (threadIdx.x < 4) {
        float t = 0.f;
#pragma unroll
        for (int w = 0; w < 8; w++) t += red[w][threadIdx.x];
        a[r0 + threadIdx.x] = mu / t;
    }
}

// ---------------- col matvec, fused combine (last-block pattern) -------------
// grid (8, COLCH), 128 threads. Each block: 8 cols/thread x 128 rows.
__global__ void __launch_bounds__(128) col_partial_kernel(const __half* __restrict__ Km,
                                                          const float* __restrict__ a,
                                                          float* __restrict__ part,
                                                          float* __restrict__ b, float nu) {
    int j8 = blockIdx.x * 128 + threadIdx.x;          // uint4 column index (8 cols)
    int r0 = blockIdx.y * (NX / COLCH);
    const uint4* base = (const uint4*)Km + (size_t)r0 * (NX / 8) + j8;
    float s[8];
#pragma unroll
    for (int q = 0; q < 8; q++) s[q] = 0.f;
#pragma unroll 4
    for (int r = 0; r < NX / COLCH; r++) {
        uint4 x = base[(size_t)r * (NX / 8)];
        float av = __ldg(&a[r0 + r]);
        const __half2* hx = (const __half2*)&x;
#pragma unroll
        for (int q = 0; q < 4; q++) {
            float2 f = __half22float2(hx[q]);
            s[q * 2] += f.x * av;
            s[q * 2 + 1] += f.y * av;
        }
    }
    size_t o = (size_t)blockIdx.y * NX + (size_t)j8 * 8;
    *(float4*)(part + o) = make_float4(s[0], s[1], s[2], s[3]);
    *(float4*)(part + o + 4) = make_float4(s[4], s[5], s[6], s[7]);

    // last y-block for this x-slice combines
    __threadfence();
    __syncthreads();
    __shared__ int isLast;
    if (threadIdx.x == 0) {
        int old = atomicAdd(&g_cnt[blockIdx.x], 1);
        isLast = (old == COLCH - 1);
        if (isLast) g_cnt[blockIdx.x] = 0;   // reset for next launch / replay
    }
    __syncthreads();
    if (isLast) {
        __threadfence();
#pragma unroll
        for (int q = 0; q < 8; q++) {
            int j = blockIdx.x * 1024 + q * 128 + threadIdx.x;
            float t = 0.f;
#pragma unroll 8
            for (int c = 0; c < COLCH; c++) t += part[(size_t)c * NX + j];
            b[j] = nu / t;
        }
    }
}

// ---------------- misc -------------------------------------------------------
__global__ void __launch_bounds__(256) ones_kernel(float* __restrict__ p) {
    p[blockIdx.x * 256 + threadIdx.x] = 1.0f;
}

__global__ void __launch_bounds__(256) log_kernel(const float* __restrict__ a,
                                                  const float* __restrict__ b,
                                                  float* __restrict__ la,
                                                  float* __restrict__ lb) {
    int i = blockIdx.x * 256 + threadIdx.x;
    la[i] = __logf(a[i]);
    lb[i] = __logf(b[i]);
}

__global__ void __launch_bounds__(256) epilogue_kernel(const __half* __restrict__ Km,
                                                       const float* __restrict__ a,
                                                       const float* __restrict__ b,
                                                       const float* __restrict__ la,
                                                       const float* __restrict__ lb,
                                                       float* __restrict__ plan,
                                                       float* __restrict__ logplan) {
    int row = blockIdx.y;
    int c8 = blockIdx.x * 256 + threadIdx.x;
    size_t kidx = (size_t)row * (NX / 8) + c8;
    uint4 x = ((const uint4*)Km)[kidx];
    const __half2* hx = (const __half2*)&x;
    float av = a[row];
    float ul = la[row];
    float kf[8];
#pragma unroll
    for (int q = 0; q < 4; q++) {
        float2 f = __half22float2(hx[q]);
        kf[q * 2] = f.x; kf[q * 2 + 1] = f.y;
    }
    float4 bb0 = ((const float4*)b)[c8 * 2];
    float4 bb1 = ((const float4*)b)[c8 * 2 + 1];
    float4 lv0 = ((const float4*)lb)[c8 * 2];
    float4 lv1 = ((const float4*)lb)[c8 * 2 + 1];
    float bv[8] = {bb0.x, bb0.y, bb0.z, bb0.w, bb1.x, bb1.y, bb1.z, bb1.w};
    float lvv[8] = {lv0.x, lv0.y, lv0.z, lv0.w, lv1.x, lv1.y, lv1.z, lv1.w};
    float p[8], lp[8];
#pragma unroll
    for (int q = 0; q < 8; q++) {
        p[q] = (kf[q] * av) * bv[q];
        lp[q] = __logf(kf[q]) + ul + lvv[q];
    }
    size_t o4 = (size_t)row * (NX / 4) + (size_t)c8 * 2;
    ((float4*)plan)[o4] = make_float4(p[0], p[1], p[2], p[3]);
    ((float4*)plan)[o4 + 1] = make_float4(p[4], p[5], p[6], p[7]);
    ((float4*)logplan)[o4] = make_float4(lp[0], lp[1], lp[2], lp[3]);
    ((float4*)logplan)[o4 + 1] = make_float4(lp[4], lp[5], lp[6], lp[7]);
}

// ---------------- launch -----------------------------------------------------
extern "C" void kernel_launch(void* const* d_in, const int* in_sizes, int n_in,
                              void* d_out, int out_size) {
    const float* X  = (const float*)d_in[0];
    const float* Y  = (const float*)d_in[1];
    const float* aX = (const float*)d_in[2];
    const float* aY = (const float*)d_in[3];
    float* out = (float*)d_out;

    __half* pK;
    float *pSX, *pSY, *pinvX, *pinvY, *pinvAX, *pinvAY, *pinvSX, *pinvSY;
    float *pa, *pb, *pla, *plb, *ppart;
    cudaGetSymbolAddress((void**)&pK, g_K);
    cudaGetSymbolAddress((void**)&pSX, g_SimX);
    cudaGetSymbolAddress((void**)&pSY, g_SimY);
    cudaGetSymbolAddress((void**)&pinvX, g_invX);
    cudaGetSymbolAddress((void**)&pinvY, g_invY);
    cudaGetSymbolAddress((void**)&pinvAX, g_invAX);
    cudaGetSymbolAddress((void**)&pinvAY, g_invAY);
    cudaGetSymbolAddress((void**)&pinvSX, g_invSX);
    cudaGetSymbolAddress((void**)&pinvSY, g_invSY);
    cudaGetSymbolAddress((void**)&pa, g_a);
    cudaGetSymbolAddress((void**)&pb, g_b);
    cudaGetSymbolAddress((void**)&pla, g_la);
    cudaGetSymbolAddress((void**)&plb, g_lb);
    cudaGetSymbolAddress((void**)&ppart, g_part);

    const float MU = 1.0f / 8192.0f;

    // 1) inverse row norms
    rownorm_kernel<<<NX, 256>>>(X, pinvX, D_DIM);
    rownorm_kernel<<<NX, 256>>>(Y, pinvY, D_DIM);
    rownorm_kernel<<<KANC, 256>>>(aX, pinvAX, D_DIM);
    rownorm_kernel<<<KANC, 256>>>(aY, pinvAY, D_DIM);

    // 2) similarity profiles (f32x2 FFMA GEMM, A-dup smem)
    gemm_nt_kernel<<<dim3(KANC / GBN, NX / GBM), 256>>>(X, aX, pSX, (__half*)0, pinvX, pinvAX,
                                                        NX, KANC, D_DIM, 1.0f, 0);
    gemm_nt_kernel<<<dim3(KANC / GBN, NX / GBM), 256>>>(Y, aY, pSY, (__half*)0, pinvY, pinvAY,
                                                        NX, KANC, D_DIM, 1.0f, 0);

    // 3) profile inverse norms
    rownorm_kernel<<<NX, 256>>>(pSX, pinvSX, KANC);
    rownorm_kernel<<<NX, 256>>>(pSY, pinvSY, KANC);

    // 4) K = exp(cos/eps), fp16
    gemm_nt_kernel<<<dim3(NX / GBN, NX / GBM), 256>>>(pSX, pSY, (float*)0, pK, pinvSX, pinvSY,
                                                      NX, NX, KANC, EPS_INV, 1);

    // 5) sinkhorn, exp domain
    ones_kernel<<<NX / 256, 256>>>(pb);
    for (int it = 0; it < NITERS; it++) {
        row_matvec_kernel<<<NX / 4, 256>>>(pK, pb, pa, MU);
        col_partial_kernel<<<dim3(8, COLCH), 128>>>(pK, pa, ppart, pb, MU);
    }
    log_kernel<<<NX / 256, 256>>>(pa, pb, pla, plb);

    // 6) outputs
    epilogue_kernel<<<dim3(NX / (256 * 8), NX), 256>>>(pK, pa, pb, pla, plb,
                                                       out, out + (size_t)NX * NX);
}

// round 13
// speedup vs baseline: 1.3756x; 1.3756x over previous
#include <cuda_runtime.h>
#include <cuda_fp16.h>
#include <math.h>

// Problem dims (fixed by setup_inputs): nx=ny=8192, d=1024, K=512, n_iters=50
#define NX 8192
#define D_DIM 1024
#define KANC 512
#define NITERS 50
#define COLCH 64           // row-chunks for the column pass
#define EPS_INV 20.0f      // 1/0.05

// ---------------- scratch (static device memory; no allocations) -------------
__device__ __align__(16) __half g_K[(size_t)NX * NX];      // exp(cos/eps), 128 MB
__device__ __align__(16) float g_SimX[(size_t)NX * KANC];  // 16 MB
__device__ __align__(16) float g_SimY[(size_t)NX * KANC];  // 16 MB
__device__ __align__(16) float g_invX[NX];
__device__ __align__(16) float g_invY[NX];
__device__ __align__(16) float g_invAX[KANC];
__device__ __align__(16) float g_invAY[KANC];
__device__ __align__(16) float g_invSX[NX];
__device__ __align__(16) float g_invSY[NX];
__device__ __align__(16) float g_a[NX];    // a = exp(u/eps)
__device__ __align__(16) float g_b[NX];    // b = exp(v/eps)
__device__ __align__(16) float g_la[NX];   // log a
__device__ __align__(16) float g_lb[NX];   // log b
__device__ __align__(16) float g_part[(size_t)COLCH * NX]; // column-pass partials

// ---------------- f32x2 helpers ----------------------------------------------
__device__ __forceinline__ unsigned long long pack2(float x, float y) {
    unsigned long long r;
    asm("mov.b64 %0, {%1, %2};" : "=l"(r) : "f"(x), "f"(y));
    return r;
}
__device__ __forceinline__ void unpack2(unsigned long long p, float& x, float& y) {
    asm("mov.b64 {%0, %1}, %2;" : "=f"(x), "=f"(y) : "l"(p));
}
__device__ __forceinline__ unsigned long long fma2(unsigned long long a,
                                                   unsigned long long b,
                                                   unsigned long long c) {
    unsigned long long d;
    asm("fma.rn.f32x2 %0, %1, %2, %3;" : "=l"(d) : "l"(a), "l"(b), "l"(c));
    return d;
}

// ---------------- row L2-norm (inverse norms) --------------------------------
__global__ void __launch_bounds__(256) rownorm_kernel(const float* __restrict__ A,
                                                      float* __restrict__ inv, int ncols) {
    int row = blockIdx.x;
    const float4* a4 = (const float4*)(A + (size_t)row * ncols);
    int n4 = ncols >> 2;
    float s = 0.f;
    for (int c = threadIdx.x; c < n4; c += 256) {
        float4 x = a4[c];
        s += x.x * x.x + x.y * x.y + x.z * x.z + x.w * x.w;
    }
#pragma unroll
    for (int o = 16; o; o >>= 1) s += __shfl_xor_sync(0xffffffffu, s, o);
    __shared__ float red[8];
    int lane = threadIdx.x & 31, wid = threadIdx.x >> 5;
    if (lane == 0) red[wid] = s;
    __syncthreads();
    if (threadIdx.x == 0) {
        float t = 0.f;
#pragma unroll
        for (int w = 0; w < 8; w++) t += red[w];
        inv[row] = 1.0f / fmaxf(sqrtf(t), 1e-8f);
    }
}

// ---------------- NT GEMM (f32x2) with scaling; fp32 out or exp->fp16 out ----
// do_exp==0: C[i,j]  = alpha*sa[i]*sb[j]*dot   (float out)
// do_exp==1: Ch[i,j] = exp(alpha*sa[i]*sb[j]*dot)  (half out)
#define GBM 128
#define GBN 128
#define GBK 16

__global__ void __launch_bounds__(256) gemm_nt_kernel(const float* __restrict__ A,
                                                      const float* __restrict__ B,
                                                      float* __restrict__ C,
                                                      __half* __restrict__ Ch,
                                                      const float* __restrict__ sa,
                                                      const float* __restrict__ sb,
                                                      int M, int N, int K, float alpha,
                                                      int do_exp) {
    __shared__ float As[GBK][GBM + 4];
    __shared__ float Bs[GBK][GBN + 4];
    int tid = threadIdx.x;
    int bm = blockIdx.y, bn = blockIdx.x;
    const float* Ab = A + (size_t)bm * GBM * K;
    const float* Bb = B + (size_t)bn * GBN * K;

    int tx = tid & 15;   // N dir
    int ty = tid >> 4;   // M dir
    int lr = tid >> 2;          // loader row
    int lc = (tid & 3) * 4;     // loader col

    unsigned long long acc[4][8];   // [i-pair][j]
#pragma unroll
    for (int ip = 0; ip < 4; ip++)
#pragma unroll
        for (int j = 0; j < 8; j++) acc[ip][j] = 0ULL;

    for (int k0 = 0; k0 < K; k0 += GBK) {
#pragma unroll
        for (int sgm = 0; sgm < 2; sgm++) {
            int r = lr + 64 * sgm;
            float4 a4 = *(const float4*)(Ab + (size_t)r * K + k0 + lc);
            As[lc + 0][r] = a4.x; As[lc + 1][r] = a4.y;
            As[lc + 2][r] = a4.z; As[lc + 3][r] = a4.w;
            float4 b4 = *(const float4*)(Bb + (size_t)r * K + k0 + lc);
            Bs[lc + 0][r] = b4.x; Bs[lc + 1][r] = b4.y;
            Bs[lc + 2][r] = b4.z; Bs[lc + 3][r] = b4.w;
        }
        __syncthreads();
#pragma unroll
        for (int kk = 0; kk < GBK; kk++) {
            float4 a0 = *(const float4*)&As[kk][ty * 4];
            float4 a1 = *(const float4*)&As[kk][ty * 4 + 64];
            float4 b0 = *(const float4*)&Bs[kk][tx * 4];
            float4 b1 = *(const float4*)&Bs[kk][tx * 4 + 64];
            unsigned long long ap[4];
            ap[0] = pack2(a0.x, a0.y); ap[1] = pack2(a0.z, a0.w);
            ap[2] = pack2(a1.x, a1.y); ap[3] = pack2(a1.z, a1.w);
            float bf[8] = {b0.x, b0.y, b0.z, b0.w, b1.x, b1.y, b1.z, b1.w};
            unsigned long long bs2[8];
#pragma unroll
            for (int j = 0; j < 8; j++) bs2[j] = pack2(bf[j], bf[j]);
#pragma unroll
            for (int ip = 0; ip < 4; ip++)
#pragma unroll
                for (int j = 0; j < 8; j++) acc[ip][j] = fma2(ap[ip], bs2[j], acc[ip][j]);
        }
        __syncthreads();
    }

#pragma unroll
    for (int ip = 0; ip < 4; ip++)
#pragma unroll
        for (int h = 0; h < 2; h++) {
            int row = bm * GBM + ty * 4 + ((ip & 1) << 1) + h + ((ip >> 1) << 6);
            float si = sa[row] * alpha;
#pragma unroll
            for (int g = 0; g < 2; g++) {
                int col = bn * GBN + tx * 4 + (g << 6);
                float v[4];
#pragma unroll
                for (int j = 0; j < 4; j++) {
                    float lo, hi;
                    unpack2(acc[ip][g * 4 + j], lo, hi);
                    v[j] = h ? hi : lo;
                }
                float4 o;
                o.x = v[0] * si * sb[col + 0];
                o.y = v[1] * si * sb[col + 1];
                o.z = v[2] * si * sb[col + 2];
                o.w = v[3] * si * sb[col + 3];
                if (do_exp) {
                    __half2 h0 = __floats2half2_rn(__expf(o.x), __expf(o.y));
                    __half2 h1 = __floats2half2_rn(__expf(o.z), __expf(o.w));
                    uint2 pk;
                    pk.x = *(unsigned int*)&h0;
                    pk.y = *(unsigned int*)&h1;
                    *(uint2*)(Ch + (size_t)row * N + col) = pk;
                } else {
                    *(float4*)(C + (size_t)row * N + col) = o;
                }
            }
        }
}

// ---------------- row matvec: a_i = mu / sum_j K_ij b_j  (8 rows/block) ------
__global__ void __launch_bounds__(256) row_matvec_kernel(const __half* __restrict__ Km,
                                                         const float* __restrict__ b,
                                                         float* __restrict__ a, float mu) {
    int r0 = blockIdx.x * 8;
    const uint4* row0 = (const uint4*)(Km + (size_t)r0 * NX);   // 1024 uint4 per row
    const float4* b4 = (const float4*)b;
    float s[8];
#pragma unroll
    for (int r = 0; r < 8; r++) s[r] = 0.f;
#pragma unroll
    for (int it = 0; it < NX / 8 / 256; it++) {
        int c = it * 256 + threadIdx.x;
        float4 bb0 = b4[c * 2], bb1 = b4[c * 2 + 1];
        float bv[8] = {bb0.x, bb0.y, bb0.z, bb0.w, bb1.x, bb1.y, bb1.z, bb1.w};
        uint4 x[8];
#pragma unroll
        for (int r = 0; r < 8; r++) x[r] = row0[c + r * (NX / 8)];
#pragma unroll
        for (int r = 0; r < 8; r++) {
            const __half2* hx = (const __half2*)&x[r];
            float accv = 0.f;
#pragma unroll
            for (int q = 0; q < 4; q++) {
                float2 f = __half22float2(hx[q]);
                accv += f.x * bv[q * 2] + f.y * bv[q * 2 + 1];
            }
            s[r] += accv;
        }
    }
#pragma unroll
    for (int o = 16; o; o >>= 1) {
#pragma unroll
        for (int r = 0; r < 8; r++) s[r] += __shfl_xor_sync(0xffffffffu, s[r], o);
    }
    __shared__ float red[8][8];
    int lane = threadIdx.x & 31, wid = threadIdx.x >> 5;
    if (lane == 0) {
#pragma unroll
        for (int r = 0; r < 8; r++) red[wid][r] = s[r];
    }
    __syncthreads();
    if (threadIdx.x < 8) {
        float t = 0.f;
#pragma unroll
        for (int w = 0; w < 8; w++) t += red[w][threadIdx.x];
        a[r0 + threadIdx.x] = mu / t;
    }
}

// ---------------- col matvec (2-stage): b_j = nu / sum_i K_ij a_i ------------
__global__ void __launch_bounds__(256) col_partial_kernel(const __half* __restrict__ Km,
                                                          const float* __restrict__ a,
                                                          float* __restrict__ part) {
    int j8 = blockIdx.x * 256 + threadIdx.x;          // uint4 column index (8 cols)
    int r0 = blockIdx.y * (NX / COLCH);
    const uint4* base = (const uint4*)Km + (size_t)r0 * (NX / 8) + j8;
    float s[8];
#pragma unroll
    for (int q = 0; q < 8; q++) s[q] = 0.f;
#pragma unroll 4
    for (int r = 0; r < NX / COLCH; r++) {
        uint4 x = base[(size_t)r * (NX / 8)];
        float av = __ldg(&a[r0 + r]);
        const __half2* hx = (const __half2*)&x;
#pragma unroll
        for (int q = 0; q < 4; q++) {
            float2 f = __half22float2(hx[q]);
            s[q * 2] += f.x * av;
            s[q * 2 + 1] += f.y * av;
        }
    }
    size_t o = (size_t)blockIdx.y * NX + (size_t)j8 * 8;
    *(float4*)(part + o) = make_float4(s[0], s[1], s[2], s[3]);
    *(float4*)(part + o + 4) = make_float4(s[4], s[5], s[6], s[7]);
}

__global__ void __launch_bounds__(256) col_combine_kernel(const float* __restrict__ part,
                                                          float* __restrict__ b, float nu) {
    int j = blockIdx.x * 256 + threadIdx.x;
    float t = 0.f;
#pragma unroll 8
    for (int c = 0; c < COLCH; c++) t += part[(size_t)c * NX + j];
    b[j] = nu / t;
}

// ---------------- misc -------------------------------------------------------
__global__ void __launch_bounds__(256) ones_kernel(float* __restrict__ p) {
    p[blockIdx.x * 256 + threadIdx.x] = 1.0f;
}

__global__ void __launch_bounds__(256) log_kernel(const float* __restrict__ a,
                                                  const float* __restrict__ b,
                                                  float* __restrict__ la,
                                                  float* __restrict__ lb) {
    int i = blockIdx.x * 256 + threadIdx.x;
    la[i] = __logf(a[i]);
    lb[i] = __logf(b[i]);
}

__global__ void __launch_bounds__(256) epilogue_kernel(const __half* __restrict__ Km,
                                                       const float* __restrict__ a,
                                                       const float* __restrict__ b,
                                                       const float* __restrict__ la,
                                                       const float* __restrict__ lb,
                                                       float* __restrict__ plan,
                                                       float* __restrict__ logplan) {
    int row = blockIdx.y;
    int c8 = blockIdx.x * 256 + threadIdx.x;      // uint4 index (8 cols): 4 blocks in x
    size_t kidx = (size_t)row * (NX / 8) + c8;
    uint4 x = ((const uint4*)Km)[kidx];
    const __half2* hx = (const __half2*)&x;
    float av = a[row];
    float ul = la[row];
    float kf[8];
#pragma unroll
    for (int q = 0; q < 4; q++) {
        float2 f = __half22float2(hx[q]);
        kf[q * 2] = f.x; kf[q * 2 + 1] = f.y;
    }
    float4 bb0 = ((const float4*)b)[c8 * 2];
    float4 bb1 = ((const float4*)b)[c8 * 2 + 1];
    float4 lv0 = ((const float4*)lb)[c8 * 2];
    float4 lv1 = ((const float4*)lb)[c8 * 2 + 1];
    float bv[8] = {bb0.x, bb0.y, bb0.z, bb0.w, bb1.x, bb1.y, bb1.z, bb1.w};
    float lvv[8] = {lv0.x, lv0.y, lv0.z, lv0.w, lv1.x, lv1.y, lv1.z, lv1.w};
    float p[8], lp[8];
#pragma unroll
    for (int q = 0; q < 8; q++) {
        p[q] = (kf[q] * av) * bv[q];
        lp[q] = __logf(kf[q]) + ul + lvv[q];
    }
    size_t o4 = (size_t)row * (NX / 4) + (size_t)c8 * 2;
    ((float4*)plan)[o4] = make_float4(p[0], p[1], p[2], p[3]);
    ((float4*)plan)[o4 + 1] = make_float4(p[4], p[5], p[6], p[7]);
    ((float4*)logplan)[o4] = make_float4(lp[0], lp[1], lp[2], lp[3]);
    ((float4*)logplan)[o4 + 1] = make_float4(lp[4], lp[5], lp[6], lp[7]);
}

// ---------------- launch -----------------------------------------------------
extern "C" void kernel_launch(void* const* d_in, const int* in_sizes, int n_in,
                              void* d_out, int out_size) {
    const float* X  = (const float*)d_in[0];
    const float* Y  = (const float*)d_in[1];
    const float* aX = (const float*)d_in[2];
    const float* aY = (const float*)d_in[3];
    float* out = (float*)d_out;

    __half* pK;
    float *pSX, *pSY, *pinvX, *pinvY, *pinvAX, *pinvAY, *pinvSX, *pinvSY;
    float *pa, *pb, *pla, *plb, *ppart;
    cudaGetSymbolAddress((void**)&pK, g_K);
    cudaGetSymbolAddress((void**)&pSX, g_SimX);
    cudaGetSymbolAddress((void**)&pSY, g_SimY);
    cudaGetSymbolAddress((void**)&pinvX, g_invX);
    cudaGetSymbolAddress((void**)&pinvY, g_invY);
    cudaGetSymbolAddress((void**)&pinvAX, g_invAX);
    cudaGetSymbolAddress((void**)&pinvAY, g_invAY);
    cudaGetSymbolAddress((void**)&pinvSX, g_invSX);
    cudaGetSymbolAddress((void**)&pinvSY, g_invSY);
    cudaGetSymbolAddress((void**)&pa, g_a);
    cudaGetSymbolAddress((void**)&pb, g_b);
    cudaGetSymbolAddress((void**)&pla, g_la);
    cudaGetSymbolAddress((void**)&plb, g_lb);
    cudaGetSymbolAddress((void**)&ppart, g_part);

    const float MU = 1.0f / 8192.0f;   // = nu

    // 1) inverse row norms of inputs and anchors
    rownorm_kernel<<<NX, 256>>>(X, pinvX, D_DIM);
    rownorm_kernel<<<NX, 256>>>(Y, pinvY, D_DIM);
    rownorm_kernel<<<KANC, 256>>>(aX, pinvAX, D_DIM);
    rownorm_kernel<<<KANC, 256>>>(aY, pinvAY, D_DIM);

    // 2) similarity profiles: Sim_X = norm(X) @ norm(aX)^T  (8192 x 512)
    gemm_nt_kernel<<<dim3(KANC / GBN, NX / GBM), 256>>>(X, aX, pSX, (__half*)0, pinvX, pinvAX,
                                                        NX, KANC, D_DIM, 1.0f, 0);
    gemm_nt_kernel<<<dim3(KANC / GBN, NX / GBM), 256>>>(Y, aY, pSY, (__half*)0, pinvY, pinvAY,
                                                        NX, KANC, D_DIM, 1.0f, 0);

    // 3) inverse row norms of profiles
    rownorm_kernel<<<NX, 256>>>(pSX, pinvSX, KANC);
    rownorm_kernel<<<NX, 256>>>(pSY, pinvSY, KANC);

    // 4) K = exp(cos(Sim_X, Sim_Y) / eps), stored fp16
    gemm_nt_kernel<<<dim3(NX / GBN, NX / GBM), 256>>>(pSX, pSY, (float*)0, pK, pinvSX, pinvSY,
                                                      NX, NX, KANC, EPS_INV, 1);

    // 5) sinkhorn, exp domain:  a = mu/(K b);  b = nu/(K^T a)
    ones_kernel<<<NX / 256, 256>>>(pb);
    for (int it = 0; it < NITERS; it++) {
        row_matvec_kernel<<<NX / 8, 256>>>(pK, pb, pa, MU);
        col_partial_kernel<<<dim3(NX / (256 * 8), COLCH), 256>>>(pK, pa, ppart);
        col_combine_kernel<<<NX / 256, 256>>>(ppart, pb, MU);
    }
    log_kernel<<<NX / 256, 256>>>(pa, pb, pla, plb);

    // 6) outputs: plan then log_plan
    epilogue_kernel<<<dim3(NX / (256 * 8), NX), 256>>>(pK, pa, pb, pla, plb,
                                                       out, out + (size_t)NX * NX);
}

// round 17
// speedup vs baseline: 1.7353x; 1.2615x over previous
#include <cuda_runtime.h>
#include <cuda_fp16.h>
#include <cstdint>
#include <math.h>

// Problem dims (fixed by setup_inputs): nx=ny=8192, d=1024, K=512, n_iters=50
#define NX 8192
#define D_DIM 1024
#define KANC 512
#define NITERS 50
#define COLCH 64           // row-chunks for the column pass
#define EPS_INV 20.0f      // 1/0.05

// ---------------- scratch (static device memory; no allocations) -------------
__device__ __align__(16) __half g_K[(size_t)NX * NX];      // exp(cos/eps), 128 MB
__device__ __align__(16) float g_SimX[(size_t)NX * KANC];  // 16 MB
__device__ __align__(16) float g_SimY[(size_t)NX * KANC];  // 16 MB
__device__ __align__(16) __half g_SXh[(size_t)NX * KANC];  // fp16(20 * norm profile X)
__device__ __align__(16) __half g_SYh[(size_t)NX * KANC];  // fp16(norm profile Y)
__device__ __align__(16) float g_invX[NX];
__device__ __align__(16) float g_invY[NX];
__device__ __align__(16) float g_invAX[KANC];
__device__ __align__(16) float g_invAY[KANC];
__device__ __align__(16) float g_invSX[NX];
__device__ __align__(16) float g_invSY[NX];
__device__ __align__(16) float g_a[NX];    // a = exp(u/eps)
__device__ __align__(16) float g_b[NX];    // b = exp(v/eps)
__device__ __align__(16) float g_la[NX];   // log a
__device__ __align__(16) float g_lb[NX];   // log b
__device__ __align__(16) float g_part[(size_t)COLCH * NX]; // column-pass partials

// ---------------- f32x2 helpers ----------------------------------------------
__device__ __forceinline__ unsigned long long pack2(float x, float y) {
    unsigned long long r;
    asm("mov.b64 %0, {%1, %2};" : "=l"(r) : "f"(x), "f"(y));
    return r;
}
__device__ __forceinline__ void unpack2(unsigned long long p, float& x, float& y) {
    asm("mov.b64 {%0, %1}, %2;" : "=f"(x), "=f"(y) : "l"(p));
}
__device__ __forceinline__ unsigned long long fma2(unsigned long long a,
                                                   unsigned long long b,
                                                   unsigned long long c) {
    unsigned long long d;
    asm("fma.rn.f32x2 %0, %1, %2, %3;" : "=l"(d) : "l"(a), "l"(b), "l"(c));
    return d;
}

// ---------------- mma helpers ------------------------------------------------
__device__ __forceinline__ unsigned smaddr(const void* p) {
    return (unsigned)__cvta_generic_to_shared(p);
}
__device__ __forceinline__ void ldsm_x4(unsigned addr, unsigned& r0, unsigned& r1,
                                        unsigned& r2, unsigned& r3) {
    asm volatile("ldmatrix.sync.aligned.m8n8.x4.shared.b16 {%0,%1,%2,%3}, [%4];\n"
                 : "=r"(r0), "=r"(r1), "=r"(r2), "=r"(r3) : "r"(addr));
}
__device__ __forceinline__ void mma16816(float* c, const unsigned* a, unsigned b0, unsigned b1) {
    asm volatile("mma.sync.aligned.m16n8k16.row.col.f32.f16.f16.f32 "
                 "{%0,%1,%2,%3},{%4,%5,%6,%7},{%8,%9},{%0,%1,%2,%3};\n"
                 : "+f"(c[0]), "+f"(c[1]), "+f"(c[2]), "+f"(c[3])
                 : "r"(a[0]), "r"(a[1]), "r"(a[2]), "r"(a[3]), "r"(b0), "r"(b1));
}
#define CP16(dst, src) asm volatile("cp.async.cg.shared.global [%0], [%1], 16;\n" ::"r"(dst), "l"(src))
#define CPCOMMIT() asm volatile("cp.async.commit_group;\n")
#define CPWAIT1() asm volatile("cp.async.wait_group 1;\n" ::: "memory")
#define CPWAIT0() asm volatile("cp.async.wait_group 0;\n" ::: "memory")

// ---------------- row L2-norm ------------------------------------------------
__global__ void __launch_bounds__(256) rownorm_kernel(const float* __restrict__ A,
                                                      float* __restrict__ inv, int ncols) {
    int row = blockIdx.x;
    const float4* a4 = (const float4*)(A + (size_t)row * ncols);
    int n4 = ncols >> 2;
    float s = 0.f;
    for (int c = threadIdx.x; c < n4; c += 256) {
        float4 x = a4[c];
        s += x.x * x.x + x.y * x.y + x.z * x.z + x.w * x.w;
    }
#pragma unroll
    for (int o = 16; o; o >>= 1) s += __shfl_xor_sync(0xffffffffu, s, o);
    __shared__ float red[8];
    int lane = threadIdx.x & 31, wid = threadIdx.x >> 5;
    if (lane == 0) red[wid] = s;
    __syncthreads();
    if (threadIdx.x == 0) {
        float t = 0.f;
#pragma unroll
        for (int w = 0; w < 8; w++) t += red[w];
        inv[row] = 1.0f / fmaxf(sqrtf(t), 1e-8f);
    }
}

// ---------------- small NT GEMM (f32x2), float out ---------------------------
#define GBM 128
#define GBN 128
#define GBK 16

__global__ void __launch_bounds__(256) gemm_nt_kernel(const float* __restrict__ A,
                                                      const float* __restrict__ B,
                                                      float* __restrict__ C,
                                                      const float* __restrict__ sa,
                                                      const float* __restrict__ sb,
                                                      int M, int N, int K, float alpha) {
    __shared__ float As[GBK][GBM + 4];
    __shared__ float Bs[GBK][GBN + 4];
    int tid = threadIdx.x;
    int bm = blockIdx.y, bn = blockIdx.x;
    const float* Ab = A + (size_t)bm * GBM * K;
    const float* Bb = B + (size_t)bn * GBN * K;

    int tx = tid & 15;
    int ty = tid >> 4;
    int lr = tid >> 2;
    int lc = (tid & 3) * 4;

    unsigned long long acc[4][8];
#pragma unroll
    for (int ip = 0; ip < 4; ip++)
#pragma unroll
        for (int j = 0; j < 8; j++) acc[ip][j] = 0ULL;

    for (int k0 = 0; k0 < K; k0 += GBK) {
#pragma unroll
        for (int sgm = 0; sgm < 2; sgm++) {
            int r = lr + 64 * sgm;
            float4 a4 = *(const float4*)(Ab + (size_t)r * K + k0 + lc);
            As[lc + 0][r] = a4.x; As[lc + 1][r] = a4.y;
            As[lc + 2][r] = a4.z; As[lc + 3][r] = a4.w;
            float4 b4 = *(const float4*)(Bb + (size_t)r * K + k0 + lc);
            Bs[lc + 0][r] = b4.x; Bs[lc + 1][r] = b4.y;
            Bs[lc + 2][r] = b4.z; Bs[lc + 3][r] = b4.w;
        }
        __syncthreads();
#pragma unroll
        for (int kk = 0; kk < GBK; kk++) {
            float4 a0 = *(const float4*)&As[kk][ty * 4];
            float4 a1 = *(const float4*)&As[kk][ty * 4 + 64];
            float4 b0 = *(const float4*)&Bs[kk][tx * 4];
            float4 b1 = *(const float4*)&Bs[kk][tx * 4 + 64];
            unsigned long long ap[4];
            ap[0] = pack2(a0.x, a0.y); ap[1] = pack2(a0.z, a0.w);
            ap[2] = pack2(a1.x, a1.y); ap[3] = pack2(a1.z, a1.w);
            float bf[8] = {b0.x, b0.y, b0.z, b0.w, b1.x, b1.y, b1.z, b1.w};
            unsigned long long bs2[8];
#pragma unroll
            for (int j = 0; j < 8; j++) bs2[j] = pack2(bf[j], bf[j]);
#pragma unroll
            for (int ip = 0; ip < 4; ip++)
#pragma unroll
                for (int j = 0; j < 8; j++) acc[ip][j] = fma2(ap[ip], bs2[j], acc[ip][j]);
        }
        __syncthreads();
    }

#pragma unroll
    for (int ip = 0; ip < 4; ip++)
#pragma unroll
        for (int h = 0; h < 2; h++) {
            int row = bm * GBM + ty * 4 + ((ip & 1) << 1) + h + ((ip >> 1) << 6);
            float si = sa[row] * alpha;
#pragma unroll
            for (int g = 0; g < 2; g++) {
                int col = bn * GBN + tx * 4 + (g << 6);
                float v[4];
#pragma unroll
                for (int j = 0; j < 4; j++) {
                    float lo, hi;
                    unpack2(acc[ip][g * 4 + j], lo, hi);
                    v[j] = h ? hi : lo;
                }
                float4 o;
                o.x = v[0] * si * sb[col + 0];
                o.y = v[1] * si * sb[col + 1];
                o.z = v[2] * si * sb[col + 2];
                o.w = v[3] * si * sb[col + 3];
                *(float4*)(C + (size_t)row * N + col) = o;
            }
        }
}

// ---------------- split: alpha * normalized profile -> fp16 ------------------
__global__ void __launch_bounds__(256) split_kernel(const float* __restrict__ S,
                                                    const float* __restrict__ inv,
                                                    __half* __restrict__ H, float alpha) {
    int row = blockIdx.y;
    int c = blockIdx.x * 256 + threadIdx.x;
    float v = S[(size_t)row * KANC + c] * inv[row] * alpha;
    H[(size_t)row * KANC + c] = __float2half_rn(v);
}

// ---------------- HMMA GEMM: K = exp(Ah . Bh^T), fp16 out --------------------
// A pre-scaled by 20. Tile 128x128x32, 8 warps (warp tile 32x64), 1-term fp16.
#define MMS 40                       // smem row stride (halves): conflict-free
#define MMBUF (128 * MMS)            // halves per matrix per buffer

__global__ void __launch_bounds__(256) hmma_exp_kernel(const __half* __restrict__ Ah,
                                                       const __half* __restrict__ Bh,
                                                       __half* __restrict__ Kout) {
    __shared__ __half sA[2][MMBUF];
    __shared__ __half sB[2][MMBUF];

    int tid = threadIdx.x;
    int bm = blockIdx.y, bn = blockIdx.x;
    const __half* gA = Ah + (size_t)bm * 128 * KANC;
    const __half* gB = Bh + (size_t)bn * 128 * KANC;

    int wid = tid >> 5, lane = tid & 31;
    int wm = (wid & 3) * 32;     // warp m offset
    int wn = (wid >> 2) * 64;    // warp n offset
    int lrow = lane & 15;
    int lk8 = (lane >> 4) << 3;

    float acc[2][8][4];
#pragma unroll
    for (int mt = 0; mt < 2; mt++)
#pragma unroll
        for (int nt = 0; nt < 8; nt++)
#pragma unroll
            for (int q = 0; q < 4; q++) acc[mt][nt][q] = 0.f;

    // loader: chunk of 32 k-halves for A and B into buffer buf
    auto load_chunk = [&](int buf, int k0) {
#pragma unroll
        for (int t = 0; t < 4; t++) {
            int idx = t * 256 + tid;         // 0..1023
            int mat = idx >> 9;              // 0 = A, 1 = B
            int within = idx & 511;
            int row = within >> 2;
            int col = (within & 3) << 3;     // halves
            const __half* src = (mat ? gB : gA) + (size_t)row * KANC + k0 + col;
            unsigned dst = smaddr((mat ? sB[buf] : sA[buf]) + row * MMS + col);
            CP16(dst, src);
        }
        CPCOMMIT();
    };

    load_chunk(0, 0);
    const int NITER = KANC / 32;   // 16
    for (int it = 0; it < NITER; it++) {
        int buf = it & 1;
        if (it + 1 < NITER) {
            load_chunk(buf ^ 1, (it + 1) * 32);
            CPWAIT1();             // current buf's group is done
        } else {
            CPWAIT0();
        }
        __syncthreads();           // all warps see buf loaded
#pragma unroll
        for (int k16 = 0; k16 < 2; k16++) {
            int kb = k16 * 16 + lk8;
            unsigned a[2][4];
#pragma unroll
            for (int mt = 0; mt < 2; mt++) {
                unsigned r = smaddr(sA[buf] + (wm + mt * 16 + lrow) * MMS + kb);
                ldsm_x4(r, a[mt][0], a[mt][1], a[mt][2], a[mt][3]);
            }
            unsigned b[4][4];
#pragma unroll
            for (int p = 0; p < 4; p++) {
                unsigned r = smaddr(sB[buf] + (wn + p * 16 + lrow) * MMS + kb);
                ldsm_x4(r, b[p][0], b[p][1], b[p][2], b[p][3]);
            }
#pragma unroll
            for (int mt = 0; mt < 2; mt++)
#pragma unroll
                for (int nt = 0; nt < 8; nt++) {
                    int p = nt >> 1, w = nt & 1;
                    mma16816(acc[mt][nt], a[mt], b[p][w], b[p][w + 2]);
                }
        }
        __syncthreads();           // done reading buf before it is overwritten
    }

    // epilogue: exp, half2 stores
    int r0 = lane >> 2;
    int cc = (lane & 3) * 2;
#pragma unroll
    for (int mt = 0; mt < 2; mt++)
#pragma unroll
        for (int nt = 0; nt < 8; nt++) {
            int col = bn * 128 + wn + nt * 8 + cc;
            int rowa = bm * 128 + wm + mt * 16 + r0;
            __half2 h0 = __floats2half2_rn(__expf(acc[mt][nt][0]), __expf(acc[mt][nt][1]));
            __half2 h1 = __floats2half2_rn(__expf(acc[mt][nt][2]), __expf(acc[mt][nt][3]));
            *(__half2*)(Kout + (size_t)rowa * NX + col) = h0;
            *(__half2*)(Kout + (size_t)(rowa + 8) * NX + col) = h1;
        }
}

// ---------------- row matvec: a_i = mu / sum_j K_ij b_j  (4 rows/block) ------
__global__ void __launch_bounds__(256) row_matvec_kernel(const __half* __restrict__ Km,
                                                         const float* __restrict__ b,
                                                         float* __restrict__ a, float mu) {
    int r0 = blockIdx.x * 4;
    const uint4* row0 = (const uint4*)(Km + (size_t)r0 * NX);
    const float4* b4 = (const float4*)b;
    float s0 = 0.f, s1 = 0.f, s2 = 0.f, s3 = 0.f;
#pragma unroll
    for (int it = 0; it < NX / 8 / 256; it++) {
        int c = it * 256 + threadIdx.x;
        float4 bb0 = b4[c * 2], bb1 = b4[c * 2 + 1];
        float bv[8] = {bb0.x, bb0.y, bb0.z, bb0.w, bb1.x, bb1.y, bb1.z, bb1.w};
#pragma unroll
        for (int r = 0; r < 4; r++) {
            uint4 x = row0[c + r * (NX / 8)];
            const __half2* hx = (const __half2*)&x;
            float accv = 0.f;
#pragma unroll
            for (int q = 0; q < 4; q++) {
                float2 f = __half22float2(hx[q]);
                accv += f.x * bv[q * 2] + f.y * bv[q * 2 + 1];
            }
            if (r == 0) s0 += accv;
            else if (r == 1) s1 += accv;
            else if (r == 2) s2 += accv;
            else s3 += accv;
        }
    }
#pragma unroll
    for (int o = 16; o; o >>= 1) {
        s0 += __shfl_xor_sync(0xffffffffu, s0, o);
        s1 += __shfl_xor_sync(0xffffffffu, s1, o);
        s2 += __shfl_xor_sync(0xffffffffu, s2, o);
        s3 += __shfl_xor_sync(0xffffffffu, s3, o);
    }
    __shared__ float red[8][4];
    int lane = threadIdx.x & 31, wid = threadIdx.x >> 5;
    if (lane == 0) { red[wid][0] = s0; red[wid][1] = s1; red[wid][2] = s2; red[wid][3] = s3; }
    __syncthreads();
    if (threadIdx.x < 4) {
        float t = 0.f;
#pragma unroll
        for (int w = 0; w < 8; w++) t += red[w][threadIdx.x];
        a[r0 + threadIdx.x] = mu / t;
    }
}

// ---------------- col matvec (2-stage): b_j = nu / sum_i K_ij a_i ------------
__global__ void __launch_bounds__(256) col_partial_kernel(const __half* __restrict__ Km,
                                                          const float* __restrict__ a,
                                                          float* __restrict__ part) {
    int j8 = blockIdx.x * 256 + threadIdx.x;          // uint4 column index (8 cols)
    int r0 = blockIdx.y * (NX / COLCH);
    const uint4* base = (const uint4*)Km + (size_t)r0 * (NX / 8) + j8;
    float s[8];
#pragma unroll
    for (int q = 0; q < 8; q++) s[q] = 0.f;
#pragma unroll 4
    for (int r = 0; r < NX / COLCH; r++) {
        uint4 x = base[(size_t)r * (NX / 8)];
        float av = __ldg(&a[r0 + r]);
        const __half2* hx = (const __half2*)&x;
#pragma unroll
        for (int q = 0; q < 4; q++) {
            float2 f = __half22float2(hx[q]);
            s[q * 2] += f.x * av;
            s[q * 2 + 1] += f.y * av;
        }
    }
    size_t o = (size_t)blockIdx.y * NX + (size_t)j8 * 8;
    *(float4*)(part + o) = make_float4(s[0], s[1], s[2], s[3]);
    *(float4*)(part + o + 4) = make_float4(s[4], s[5], s[6], s[7]);
}

__global__ void __launch_bounds__(256) col_combine_kernel(const float* __restrict__ part,
                                                          float* __restrict__ b, float nu) {
    int j = blockIdx.x * 256 + threadIdx.x;
    float t = 0.f;
#pragma unroll 8
    for (int c = 0; c < COLCH; c++) t += part[(size_t)c * NX + j];
    b[j] = nu / t;
}

// ---------------- misc -------------------------------------------------------
__global__ void __launch_bounds__(256) ones_kernel(float* __restrict__ p) {
    p[blockIdx.x * 256 + threadIdx.x] = 1.0f;
}

__global__ void __launch_bounds__(256) log_kernel(const float* __restrict__ a,
                                                  const float* __restrict__ b,
                                                  float* __restrict__ la,
                                                  float* __restrict__ lb) {
    int i = blockIdx.x * 256 + threadIdx.x;
    la[i] = __logf(a[i]);
    lb[i] = __logf(b[i]);
}

__global__ void __launch_bounds__(256) epilogue_kernel(const __half* __restrict__ Km,
                                                       const float* __restrict__ a,
                                                       const float* __restrict__ b,
                                                       const float* __restrict__ la,
                                                       const float* __restrict__ lb,
                                                       float* __restrict__ plan,
                                                       float* __restrict__ logplan) {
    int row = blockIdx.y;
    int c8 = blockIdx.x * 256 + threadIdx.x;
    size_t kidx = (size_t)row * (NX / 8) + c8;
    uint4 x = ((const uint4*)Km)[kidx];
    const __half2* hx = (const __half2*)&x;
    float av = a[row];
    float ul = la[row];
    float kf[8];
#pragma unroll
    for (int q = 0; q < 4; q++) {
        float2 f = __half22float2(hx[q]);
        kf[q * 2] = f.x; kf[q * 2 + 1] = f.y;
    }
    float4 bb0 = ((const float4*)b)[c8 * 2];
    float4 bb1 = ((const float4*)b)[c8 * 2 + 1];
    float4 lv0 = ((const float4*)lb)[c8 * 2];
    float4 lv1 = ((const float4*)lb)[c8 * 2 + 1];
    float bv[8] = {bb0.x, bb0.y, bb0.z, bb0.w, bb1.x, bb1.y, bb1.z, bb1.w};
    float lvv[8] = {lv0.x, lv0.y, lv0.z, lv0.w, lv1.x, lv1.y, lv1.z, lv1.w};
    float p[8], lp[8];
#pragma unroll
    for (int q = 0; q < 8; q++) {
        p[q] = (kf[q] * av) * bv[q];
        lp[q] = __logf(kf[q]) + ul + lvv[q];
    }
    size_t o4 = (size_t)row * (NX / 4) + (size_t)c8 * 2;
    ((float4*)plan)[o4] = make_float4(p[0], p[1], p[2], p[3]);
    ((float4*)plan)[o4 + 1] = make_float4(p[4], p[5], p[6], p[7]);
    ((float4*)logplan)[o4] = make_float4(lp[0], lp[1], lp[2], lp[3]);
    ((float4*)logplan)[o4 + 1] = make_float4(lp[4], lp[5], lp[6], lp[7]);
}

// ---------------- launch -----------------------------------------------------
extern "C" void kernel_launch(void* const* d_in, const int* in_sizes, int n_in,
                              void* d_out, int out_size) {
    const float* X  = (const float*)d_in[0];
    const float* Y  = (const float*)d_in[1];
    const float* aX = (const float*)d_in[2];
    const float* aY = (const float*)d_in[3];
    float* out = (float*)d_out;

    __half *pK, *pSXh, *pSYh;
    float *pSX, *pSY, *pinvX, *pinvY, *pinvAX, *pinvAY, *pinvSX, *pinvSY;
    float *pa, *pb, *pla, *plb, *ppart;
    cudaGetSymbolAddress((void**)&pK, g_K);
    cudaGetSymbolAddress((void**)&pSX, g_SimX);
    cudaGetSymbolAddress((void**)&pSY, g_SimY);
    cudaGetSymbolAddress((void**)&pSXh, g_SXh);
    cudaGetSymbolAddress((void**)&pSYh, g_SYh);
    cudaGetSymbolAddress((void**)&pinvX, g_invX);
    cudaGetSymbolAddress((void**)&pinvY, g_invY);
    cudaGetSymbolAddress((void**)&pinvAX, g_invAX);
    cudaGetSymbolAddress((void**)&pinvAY, g_invAY);
    cudaGetSymbolAddress((void**)&pinvSX, g_invSX);
    cudaGetSymbolAddress((void**)&pinvSY, g_invSY);
    cudaGetSymbolAddress((void**)&pa, g_a);
    cudaGetSymbolAddress((void**)&pb, g_b);
    cudaGetSymbolAddress((void**)&pla, g_la);
    cudaGetSymbolAddress((void**)&plb, g_lb);
    cudaGetSymbolAddress((void**)&ppart, g_part);

    const float MU = 1.0f / 8192.0f;   // = nu

    // 1) inverse row norms of inputs and anchors
    rownorm_kernel<<<NX, 256>>>(X, pinvX, D_DIM);
    rownorm_kernel<<<NX, 256>>>(Y, pinvY, D_DIM);
    rownorm_kernel<<<KANC, 256>>>(aX, pinvAX, D_DIM);
    rownorm_kernel<<<KANC, 256>>>(aY, pinvAY, D_DIM);

    // 2) similarity profiles: Sim_X = norm(X) @ norm(aX)^T  (8192 x 512)
    gemm_nt_kernel<<<dim3(KANC / GBN, NX / GBM), 256>>>(X, aX, pSX, pinvX, pinvAX,
                                                        NX, KANC, D_DIM, 1.0f);
    gemm_nt_kernel<<<dim3(KANC / GBN, NX / GBM), 256>>>(Y, aY, pSY, pinvY, pinvAY,
                                                        NX, KANC, D_DIM, 1.0f);

    // 3) profile inverse norms + fp16 conversion (eps folded into X side)
    rownorm_kernel<<<NX, 256>>>(pSX, pinvSX, KANC);
    rownorm_kernel<<<NX, 256>>>(pSY, pinvSY, KANC);
    split_kernel<<<dim3(KANC / 256, NX), 256>>>(pSX, pinvSX, pSXh, EPS_INV);
    split_kernel<<<dim3(KANC / 256, NX), 256>>>(pSY, pinvSY, pSYh, 1.0f);

    // 4) K = exp(20*cos), fp16, via single-term fp16 HMMA
    hmma_exp_kernel<<<dim3(NX / 128, NX / 128), 256>>>(pSXh, pSYh, pK);

    // 5) sinkhorn, exp domain:  a = mu/(K b);  b = nu/(K^T a)
    ones_kernel<<<NX / 256, 256>>>(pb);
    for (int it = 0; it < NITERS; it++) {
        row_matvec_kernel<<<NX / 4, 256>>>(pK, pb, pa, MU);
        col_partial_kernel<<<dim3(NX / (256 * 8), COLCH), 256>>>(pK, pa, ppart);
        col_combine_kernel<<<NX / 256, 256>>>(ppart, pb, MU);
    }
    log_kernel<<<NX / 256, 256>>>(pa, pb, pla, plb);

    // 6) outputs: plan then log_plan
    epilogue_kernel<<<dim3(NX / (256 * 8), NX), 256>>>(pK, pa, pb, pla, plb,
                                                       out, out + (size_t)NX * NX);
}